// round 7
// baseline (speedup 1.0000x reference)
#include <cuda_runtime.h>
#include <cuda_fp16.h>

#define NMAX 50000
#define EMAX 800000
#define E2MAX (EMAX + NMAX)
#define HC 160
#define HCP 192   // padded h1 row: 384 B, 128B-aligned
#define NH 5
#define NC 32
#define WPB 8     // warps per block in fused1 (= 4 node-pairs)

// ---- scratch (static device globals) ----
__device__ __align__(128) __half g_h1h[(size_t)NMAX * HCP];
__device__ __align__(16) float g_as1[NMAX * 8];
__device__ float g_ad1[NMAX * NH];
__device__ __align__(16) float4 g_h2f4[NMAX * 3];           // {h2,as2}x5 padded to 48B
__device__ float g_ad2[NMAX * NH];
__device__ float g_ce1[NH], g_ce2[NH];
__device__ float g_easum;
__device__ int   g_cnt[NMAX];
__device__ int   g_rowptr[NMAX + 1];
__device__ int   g_pos[E2MAX];
__device__ __align__(8) int2 g_edge[E2MAX];                 // {src, ea-bits}

// ---- combo: [count in-degree (save pos) + easum] || [node1 transform] ----
__global__ void k_combo(const int* __restrict__ dst, const float* __restrict__ ea,
                        const float* __restrict__ x, const float* __restrict__ W1,
                        const float* __restrict__ asrc, const float* __restrict__ adst,
                        int E, int N, int countBlocks) {
    if ((int)blockIdx.x < countBlocks) {
        int e = blockIdx.x * blockDim.x + threadIdx.x;
        int E2 = E + N;
        float s = 0.f;
        if (e < E2) {
            int d = (e < E) ? __ldg(&dst[e]) : (e - E);
            g_pos[e] = atomicAdd(&g_cnt[d], 1);
            if (e < E) s = __ldg(&ea[e]);
        }
        #pragma unroll
        for (int o = 16; o; o >>= 1) s += __shfl_xor_sync(~0u, s, o);
        if ((threadIdx.x & 31) == 0 && s != 0.f) atomicAdd(&g_easum, s);
    } else {
        int warp = (((int)blockIdx.x - countBlocks) * blockDim.x + threadIdx.x) >> 5;
        int lane = threadIdx.x & 31;
        if (warp >= N) return;
        int n = warp;
        float xf[5];
        #pragma unroll
        for (int f = 0; f < 5; f++) xf[f] = __ldg(&x[n * 5 + f]);
        #pragma unroll
        for (int h = 0; h < NH; h++) {
            int col = h * NC + lane;
            float acc = 0.f;
            #pragma unroll
            for (int f = 0; f < 5; f++) acc = fmaf(xf[f], __ldg(&W1[f * HC + col]), acc);
            g_h1h[(size_t)n * HCP + col] = __float2half(acc);
            float ps = acc * __ldg(&asrc[col]);
            float pd = acc * __ldg(&adst[col]);
            #pragma unroll
            for (int o = 16; o; o >>= 1) {
                ps += __shfl_xor_sync(~0u, ps, o);
                pd += __shfl_xor_sync(~0u, pd, o);
            }
            if (lane == 0) { g_as1[n * 8 + h] = ps; g_ad1[n * NH + h] = pd; }
        }
    }
}

// ---- single-block exclusive scan + attn constants ----
__global__ void k_scan(const float* __restrict__ We1, const float* __restrict__ ae1,
                       const float* __restrict__ We2, const float* __restrict__ ae2,
                       int N, int E2) {
    __shared__ int wsum[32];
    int t = threadIdx.x;
    int lane = t & 31, w = t >> 5;
    if (t < NH) {
        float s = 0.f;
        for (int c = 0; c < NC; c++) s += We1[t * NC + c] * ae1[t * NC + c];
        g_ce1[t] = s;
        g_ce2[t] = We2[t] * ae2[t];
    }
    int chunk = (N + 1023) / 1024;
    int b = t * chunk, e = min(b + chunk, N);
    int s = 0;
    for (int i = b; i < e; i++) s += g_cnt[i];
    int inc = s;
    #pragma unroll
    for (int o = 1; o < 32; o <<= 1) {
        int v = __shfl_up_sync(~0u, inc, o);
        if (lane >= o) inc += v;
    }
    if (lane == 31) wsum[w] = inc;
    __syncthreads();
    if (w == 0) {
        int v = wsum[lane];
        int iv = v;
        #pragma unroll
        for (int o = 1; o < 32; o <<= 1) {
            int u = __shfl_up_sync(~0u, iv, o);
            if (lane >= o) iv += u;
        }
        wsum[lane] = iv - v;
    }
    __syncthreads();
    int run = wsum[w] + inc - s;
    for (int i = b; i < e; i++) {
        g_rowptr[i] = run;
        run += g_cnt[i];
    }
    if (t == 0) g_rowptr[N] = E2;
}

// ---- scatter edges into CSR: atomic-free ----
__global__ void k_scatter(const int* __restrict__ src, const int* __restrict__ dst,
                          const float* __restrict__ ea, int E, int N, float invE) {
    int e = blockIdx.x * blockDim.x + threadIdx.x;
    int E2 = E + N;
    if (e >= E2) return;
    int s, d; float av;
    if (e < E) { s = __ldg(&src[e]); d = __ldg(&dst[e]); av = __ldg(&ea[e]); }
    else       { s = d = e - E; av = g_easum * invE; }
    int2 rec; rec.x = s; rec.y = __float_as_int(av);
    g_edge[__ldg(&g_rowptr[d]) + g_pos[e]] = rec;
}

// ---- FUSED1: layer1 softmax+agg + relu + layer2 transform ----
// TWO warps per dst node (split edge range at midpoint); pair combines
// partial accumulators via smem, even warp runs the epilogue.
__global__ void k_fused1(const float* __restrict__ b1, const float* __restrict__ W2,
                         const float* __restrict__ as2w, const float* __restrict__ ad2w,
                         int N) {
    __shared__ __align__(16) float s_rec[WPB][32][8];
    __shared__ __align__(16) float s_comb[WPB / 2][32][6];
    __shared__ float s_den[WPB / 2][NH];
    int gwarp = (blockIdx.x * blockDim.x + threadIdx.x) >> 5;
    int lane = threadIdx.x & 31;
    int w = threadIdx.x >> 5;       // warp in block
    int p = w >> 1;                 // pair in block
    int half = w & 1;
    int n = gwarp >> 1;
    bool active = n < N;

    int row = 0, end = 0;
    float adh[NH], ceh[NH];
    if (active) {
        int r0 = g_rowptr[n], r1 = g_rowptr[n + 1];
        int mid = r0 + ((r1 - r0 + 1) >> 1);
        row = half ? mid : r0;
        end = half ? r1 : mid;
        #pragma unroll
        for (int h = 0; h < NH; h++) {
            adh[h] = __ldg(&g_ad1[n * NH + h]);
            ceh[h] = g_ce1[h];
        }
    }
    int hA = lane >> 4;

    float ax0 = 0.f, ay0 = 0.f, ax1 = 0.f, ay1 = 0.f, ax2 = 0.f, ay2 = 0.f;
    float denh[NH] = {0.f, 0.f, 0.f, 0.f, 0.f};

    for (int base = row; base < end; base += 32) {
        int cnt = min(32, end - base);
        if (lane < cnt) {
            int2 r = g_edge[base + lane];
            int sA = r.x;
            float av = __int_as_float(r.y);
            float4 a4 = __ldg((const float4*)(g_as1 + sA * 8));
            float a5 = __ldg(&g_as1[sA * 8 + 4]);
            float lv[NH] = {a4.x, a4.y, a4.z, a4.w, a5};
            float ex[NH];
            #pragma unroll
            for (int h = 0; h < NH; h++) {
                float l = lv[h] + adh[h] + av * ceh[h];
                l = l > 0.f ? l : 0.2f * l;
                ex[h] = __expf(l);
                denh[h] += ex[h];
            }
            float2* rec = (float2*)s_rec[w][lane];
            float2 p0; p0.x = ex[0]; p0.y = ex[2];
            float2 p1; p1.x = ex[1]; p1.y = ex[3];
            float2 p2; p2.x = ex[4]; p2.y = __int_as_float(sA);
            rec[0] = p0; rec[1] = p1; rec[2] = p2;
        }
        __syncwarp();
        #pragma unroll 2
        for (int j = 0; j < cnt; j++) {
            float2 pab = *(const float2*)&s_rec[w][j][2 * hA];
            float2 p4s = *(const float2*)&s_rec[w][j][4];
            int s = __float_as_int(p4s.y);
            float a0 = pab.x, a1 = pab.y, a2 = p4s.x;
            const __half2* hb = (const __half2*)(g_h1h + (size_t)s * HCP);
            __half2 v0 = __ldg(&hb[lane]);
            __half2 v1 = __ldg(&hb[32 + lane]);
            float2 f0 = __half22float2(v0), f1 = __half22float2(v1);
            ax0 = fmaf(a0, f0.x, ax0); ay0 = fmaf(a0, f0.y, ay0);
            ax1 = fmaf(a1, f1.x, ax1); ay1 = fmaf(a1, f1.y, ay1);
            if (lane < 16) {
                __half2 v2 = __ldg(&hb[64 + lane]);
                float2 f2 = __half22float2(v2);
                ax2 = fmaf(a2, f2.x, ax2); ay2 = fmaf(a2, f2.y, ay2);
            }
        }
        __syncwarp();
    }

    // per-warp denominator reduction across lanes
    #pragma unroll
    for (int h = 0; h < NH; h++) {
        #pragma unroll
        for (int o = 16; o; o >>= 1) denh[h] += __shfl_xor_sync(~0u, denh[h], o);
    }

    // odd warp publishes partials
    if (half) {
        float* c = s_comb[p][lane];
        c[0] = ax0; c[1] = ay0; c[2] = ax1; c[3] = ay1; c[4] = ax2; c[5] = ay2;
        if (lane < NH) s_den[p][lane] = denh[lane];
    }
    __syncthreads();
    if (!active || half) return;

    // even warp merges
    {
        const float* c = s_comb[p][lane];
        ax0 += c[0]; ay0 += c[1]; ax1 += c[2]; ay1 += c[3]; ax2 += c[4]; ay2 += c[5];
        #pragma unroll
        for (int h = 0; h < NH; h++) denh[h] += s_den[p][h] + 1e-16f;
    }
    float dA = denh[hA], dB = denh[2 + hA], dC = denh[4];

    // x2 channels -> layer2 GEMV
    float a2h[NH] = {0.f, 0.f, 0.f, 0.f, 0.f};
    int k; float v;
    #define DO_CH(val, dd, kk) \
        k = (kk); v = (val) / (dd) + __ldg(&b1[k]); v = fmaxf(v, 0.f); \
        _Pragma("unroll") \
        for (int h = 0; h < NH; h++) a2h[h] = fmaf(v, __ldg(&W2[k * NH + h]), a2h[h]);
    DO_CH(ax0, dA, 2 * lane)
    DO_CH(ay0, dA, 2 * lane + 1)
    DO_CH(ax1, dB, 64 + 2 * lane)
    DO_CH(ay1, dB, 65 + 2 * lane)
    if (lane < 16) {
        DO_CH(ax2, dC, 128 + 2 * lane)
        DO_CH(ay2, dC, 129 + 2 * lane)
    }
    #undef DO_CH
    #pragma unroll
    for (int h = 0; h < NH; h++)
        #pragma unroll
        for (int o = 16; o; o >>= 1) a2h[h] += __shfl_xor_sync(~0u, a2h[h], o);
    if (lane == 0) {
        float4 p0, p1, p2;
        p0.x = a2h[0]; p0.y = a2h[0] * __ldg(&as2w[0]);
        p0.z = a2h[1]; p0.w = a2h[1] * __ldg(&as2w[1]);
        p1.x = a2h[2]; p1.y = a2h[2] * __ldg(&as2w[2]);
        p1.z = a2h[3]; p1.w = a2h[3] * __ldg(&as2w[3]);
        p2.x = a2h[4]; p2.y = a2h[4] * __ldg(&as2w[4]);
        p2.z = 0.f; p2.w = 0.f;
        g_h2f4[n * 3 + 0] = p0;
        g_h2f4[n * 3 + 1] = p1;
        g_h2f4[n * 3 + 2] = p2;
        #pragma unroll
        for (int h = 0; h < NH; h++)
            g_ad2[n * NH + h] = a2h[h] * __ldg(&ad2w[h]);
    }
}

// ---- FUSED2: layer2 softmax+agg + head-mean + Wlin + sigmoid ----
__global__ void k_fused2(const float* __restrict__ b2, const float* __restrict__ Wlin,
                         float* __restrict__ out, int N) {
    int warp = (blockIdx.x * blockDim.x + threadIdx.x) >> 5;
    int lane = threadIdx.x & 31;
    if (warp >= N) return;
    int n = warp;
    int row = g_rowptr[n], end = g_rowptr[n + 1];

    float adh[NH], ceh[NH];
    #pragma unroll
    for (int h = 0; h < NH; h++) {
        adh[h] = __ldg(&g_ad2[n * NH + h]);
        ceh[h] = g_ce2[h];
    }
    float acch[NH] = {0.f, 0.f, 0.f, 0.f, 0.f};
    float denh[NH] = {0.f, 0.f, 0.f, 0.f, 0.f};

    for (int base = row; base < end; base += 32) {
        int e = base + lane;
        if (e < end) {
            int2 r = g_edge[e];
            int s = r.x;
            float av = __int_as_float(r.y);
            float4 p0 = __ldg(&g_h2f4[s * 3 + 0]);
            float4 p1 = __ldg(&g_h2f4[s * 3 + 1]);
            float4 p2 = __ldg(&g_h2f4[s * 3 + 2]);
            float h2v[NH]  = {p0.x, p0.z, p1.x, p1.z, p2.x};
            float as2v[NH] = {p0.y, p0.w, p1.y, p1.w, p2.y};
            #pragma unroll
            for (int h = 0; h < NH; h++) {
                float l = as2v[h] + adh[h] + av * ceh[h];
                l = l > 0.f ? l : 0.2f * l;
                float ex = __expf(l);
                denh[h] += ex;
                acch[h] = fmaf(ex, h2v[h], acch[h]);
            }
        }
    }
    #pragma unroll
    for (int h = 0; h < NH; h++)
        #pragma unroll
        for (int o = 16; o; o >>= 1) {
            acch[h] += __shfl_xor_sync(~0u, acch[h], o);
            denh[h] += __shfl_xor_sync(~0u, denh[h], o);
        }
    if (lane == 0) {
        float ssum = 0.f;
        #pragma unroll
        for (int h = 0; h < NH; h++) ssum += acch[h] / (denh[h] + 1e-16f);
        float y = (ssum * (1.0f / NH) + __ldg(&b2[0])) * __ldg(&Wlin[0]);
        out[n] = 1.0f / (1.0f + expf(-y));
    }
}

extern "C" void kernel_launch(void* const* d_in, const int* in_sizes, int n_in,
                              void* d_out, int out_size) {
    const float* x      = (const float*)d_in[0];
    const float* ea     = (const float*)d_in[1];
    const int*   src    = (const int*)d_in[2];
    const int*   dst    = (const int*)d_in[3];
    const float* W1     = (const float*)d_in[4];
    const float* a_src1 = (const float*)d_in[5];
    const float* a_dst1 = (const float*)d_in[6];
    const float* We1    = (const float*)d_in[7];
    const float* ae1    = (const float*)d_in[8];
    const float* b1     = (const float*)d_in[9];
    const float* W2     = (const float*)d_in[10];
    const float* a_src2 = (const float*)d_in[11];
    const float* a_dst2 = (const float*)d_in[12];
    const float* We2    = (const float*)d_in[13];
    const float* ae2    = (const float*)d_in[14];
    const float* b2     = (const float*)d_in[15];
    const float* Wlin   = (const float*)d_in[16];

    int N  = in_sizes[0] / 5;
    int E  = in_sizes[2];
    int E2 = E + N;
    float invE = 1.0f / (float)E;

    void* cntp = nullptr; void* easp = nullptr;
    cudaGetSymbolAddress(&cntp, g_cnt);
    cudaGetSymbolAddress(&easp, g_easum);
    cudaMemsetAsync(cntp, 0, N * sizeof(int));
    cudaMemsetAsync(easp, 0, sizeof(float));

    int countBlocks = (E2 + 255) / 256;
    int nodeBlocks  = (N * 32 + 255) / 256;
    k_combo<<<countBlocks + nodeBlocks, 256>>>(dst, ea, x, W1, a_src1, a_dst1, E, N, countBlocks);
    k_scan<<<1, 1024>>>(We1, ae1, We2, ae2, N, E2);
    k_scatter<<<(E2 + 255) / 256, 256>>>(src, dst, ea, E, N, invE);
    k_fused1<<<(int)(((long)2 * N * 32 + 255) / 256), 256>>>(b1, W2, a_src2, a_dst2, N);
    k_fused2<<<(N * 32 + 255) / 256, 256>>>(b2, Wlin, (float*)d_out, N);
}

// round 8
// speedup vs baseline: 1.1299x; 1.1299x over previous
#include <cuda_runtime.h>
#include <cuda_fp16.h>

#define NMAX 50000
#define EMAX 800000
#define E2MAX (EMAX + NMAX)
#define HC 160
#define HCP 192   // padded h1 row: 384 B, 128B-aligned
#define NH 5
#define NC 32
#define WPB 8

// ---- scratch (static device globals) ----
__device__ __align__(128) __half g_h1h[(size_t)NMAX * HCP];
__device__ __align__(16) float g_as1[NMAX * 8];
__device__ float g_ad1[NMAX * NH];
__device__ __align__(16) float4 g_h2f4[NMAX * 3];           // {h2,as2}x5 padded to 48B
__device__ float g_ad2[NMAX * NH];
__device__ float g_ce1[NH], g_ce2[NH];
__device__ float g_easum;
__device__ int   g_cnt[NMAX];
__device__ int   g_rowptr[NMAX + 1];
__device__ int   g_pos[E2MAX];
__device__ __align__(8) int2 g_edge[E2MAX];                 // {src, ea-bits}

// ---- combo: [count in-degree (save pos) + easum] || [node1 transform] ----
__global__ void k_combo(const int* __restrict__ dst, const float* __restrict__ ea,
                        const float* __restrict__ x, const float* __restrict__ W1,
                        const float* __restrict__ asrc, const float* __restrict__ adst,
                        int E, int N, int countBlocks) {
    if ((int)blockIdx.x < countBlocks) {
        int e = blockIdx.x * blockDim.x + threadIdx.x;
        int E2 = E + N;
        float s = 0.f;
        if (e < E2) {
            int d = (e < E) ? __ldg(&dst[e]) : (e - E);
            g_pos[e] = atomicAdd(&g_cnt[d], 1);
            if (e < E) s = __ldg(&ea[e]);
        }
        #pragma unroll
        for (int o = 16; o; o >>= 1) s += __shfl_xor_sync(~0u, s, o);
        if ((threadIdx.x & 31) == 0 && s != 0.f) atomicAdd(&g_easum, s);
    } else {
        int warp = (((int)blockIdx.x - countBlocks) * blockDim.x + threadIdx.x) >> 5;
        int lane = threadIdx.x & 31;
        if (warp >= N) return;
        int n = warp;
        float xf[5];
        #pragma unroll
        for (int f = 0; f < 5; f++) xf[f] = __ldg(&x[n * 5 + f]);
        #pragma unroll
        for (int h = 0; h < NH; h++) {
            int col = h * NC + lane;
            float acc = 0.f;
            #pragma unroll
            for (int f = 0; f < 5; f++) acc = fmaf(xf[f], __ldg(&W1[f * HC + col]), acc);
            g_h1h[(size_t)n * HCP + col] = __float2half(acc);
            float ps = acc * __ldg(&asrc[col]);
            float pd = acc * __ldg(&adst[col]);
            #pragma unroll
            for (int o = 16; o; o >>= 1) {
                ps += __shfl_xor_sync(~0u, ps, o);
                pd += __shfl_xor_sync(~0u, pd, o);
            }
            if (lane == 0) { g_as1[n * 8 + h] = ps; g_ad1[n * NH + h] = pd; }
        }
    }
}

// ---- single-block exclusive scan + attn constants ----
__global__ void k_scan(const float* __restrict__ We1, const float* __restrict__ ae1,
                       const float* __restrict__ We2, const float* __restrict__ ae2,
                       int N, int E2) {
    __shared__ int wsum[32];
    int t = threadIdx.x;
    int lane = t & 31, w = t >> 5;
    if (t < NH) {
        float s = 0.f;
        for (int c = 0; c < NC; c++) s += We1[t * NC + c] * ae1[t * NC + c];
        g_ce1[t] = s;
        g_ce2[t] = We2[t] * ae2[t];
    }
    int chunk = (N + 1023) / 1024;
    int b = t * chunk, e = min(b + chunk, N);
    int s = 0;
    for (int i = b; i < e; i++) s += g_cnt[i];
    int inc = s;
    #pragma unroll
    for (int o = 1; o < 32; o <<= 1) {
        int v = __shfl_up_sync(~0u, inc, o);
        if (lane >= o) inc += v;
    }
    if (lane == 31) wsum[w] = inc;
    __syncthreads();
    if (w == 0) {
        int v = wsum[lane];
        int iv = v;
        #pragma unroll
        for (int o = 1; o < 32; o <<= 1) {
            int u = __shfl_up_sync(~0u, iv, o);
            if (lane >= o) iv += u;
        }
        wsum[lane] = iv - v;
    }
    __syncthreads();
    int run = wsum[w] + inc - s;
    for (int i = b; i < e; i++) {
        g_rowptr[i] = run;
        run += g_cnt[i];
    }
    if (t == 0) g_rowptr[N] = E2;
}

// ---- scatter edges into CSR: atomic-free ----
__global__ void k_scatter(const int* __restrict__ src, const int* __restrict__ dst,
                          const float* __restrict__ ea, int E, int N, float invE) {
    int e = blockIdx.x * blockDim.x + threadIdx.x;
    int E2 = E + N;
    if (e >= E2) return;
    int s, d; float av;
    if (e < E) { s = __ldg(&src[e]); d = __ldg(&dst[e]); av = __ldg(&ea[e]); }
    else       { s = d = e - E; av = g_easum * invE; }
    int2 rec; rec.x = s; rec.y = __float_as_int(av);
    g_edge[__ldg(&g_rowptr[d]) + g_pos[e]] = rec;
}

// ---- FUSED1: layer1 softmax+agg + relu + layer2 transform ----
// warp per dst node; phase A: lane-per-edge logits staged in smem;
// phase B: channel-parallel agg (2x LDS.64 + 3x LDG(half2) per edge).
__global__ void __launch_bounds__(256, 5)
k_fused1(const float* __restrict__ b1, const float* __restrict__ W2,
         const float* __restrict__ as2w, const float* __restrict__ ad2w,
         int N) {
    __shared__ __align__(16) float s_rec[WPB][32][8];
    int warp = (blockIdx.x * blockDim.x + threadIdx.x) >> 5;
    int lane = threadIdx.x & 31;
    int w = (threadIdx.x >> 5);
    if (warp >= N) return;
    int n = warp;
    int row = g_rowptr[n], end = g_rowptr[n + 1];

    float adh[NH], ceh[NH];
    #pragma unroll
    for (int h = 0; h < NH; h++) {
        adh[h] = __ldg(&g_ad1[n * NH + h]);
        ceh[h] = g_ce1[h];
    }
    int hA = lane >> 4;

    float ax0 = 0.f, ay0 = 0.f, ax1 = 0.f, ay1 = 0.f, ax2 = 0.f, ay2 = 0.f;
    float denh[NH] = {0.f, 0.f, 0.f, 0.f, 0.f};

    for (int base = row; base < end; base += 32) {
        int cnt = min(32, end - base);
        if (lane < cnt) {
            int2 r = g_edge[base + lane];
            int sA = r.x;
            float av = __int_as_float(r.y);
            float4 a4 = __ldg((const float4*)(g_as1 + sA * 8));
            float a5 = __ldg(&g_as1[sA * 8 + 4]);
            float lv[NH] = {a4.x, a4.y, a4.z, a4.w, a5};
            float ex[NH];
            #pragma unroll
            for (int h = 0; h < NH; h++) {
                float l = lv[h] + adh[h] + av * ceh[h];
                l = l > 0.f ? l : 0.2f * l;
                ex[h] = __expf(l);
                denh[h] += ex[h];
            }
            float2* rec = (float2*)s_rec[w][lane];
            float2 p0; p0.x = ex[0]; p0.y = ex[2];
            float2 p1; p1.x = ex[1]; p1.y = ex[3];
            float2 p2; p2.x = ex[4]; p2.y = __int_as_float(sA);
            rec[0] = p0; rec[1] = p1; rec[2] = p2;
        }
        __syncwarp();
        #pragma unroll 2
        for (int j = 0; j < cnt; j++) {
            float2 pab = *(const float2*)&s_rec[w][j][2 * hA];
            float2 p4s = *(const float2*)&s_rec[w][j][4];
            int s = __float_as_int(p4s.y);
            float a0 = pab.x, a1 = pab.y, a2 = p4s.x;
            const __half2* hb = (const __half2*)(g_h1h + (size_t)s * HCP);
            __half2 v0 = __ldg(&hb[lane]);
            __half2 v1 = __ldg(&hb[32 + lane]);
            float2 f0 = __half22float2(v0), f1 = __half22float2(v1);
            ax0 = fmaf(a0, f0.x, ax0); ay0 = fmaf(a0, f0.y, ay0);
            ax1 = fmaf(a1, f1.x, ax1); ay1 = fmaf(a1, f1.y, ay1);
            if (lane < 16) {
                __half2 v2 = __ldg(&hb[64 + lane]);
                float2 f2 = __half22float2(v2);
                ax2 = fmaf(a2, f2.x, ax2); ay2 = fmaf(a2, f2.y, ay2);
            }
        }
        __syncwarp();
    }

    #pragma unroll
    for (int h = 0; h < NH; h++) {
        #pragma unroll
        for (int o = 16; o; o >>= 1) denh[h] += __shfl_xor_sync(~0u, denh[h], o);
        denh[h] += 1e-16f;
    }
    float dA = denh[hA], dB = denh[2 + hA], dC = denh[4];

    float a2h[NH] = {0.f, 0.f, 0.f, 0.f, 0.f};
    int k; float v;
    #define DO_CH(val, dd, kk) \
        k = (kk); v = (val) / (dd) + __ldg(&b1[k]); v = fmaxf(v, 0.f); \
        _Pragma("unroll") \
        for (int h = 0; h < NH; h++) a2h[h] = fmaf(v, __ldg(&W2[k * NH + h]), a2h[h]);
    DO_CH(ax0, dA, 2 * lane)
    DO_CH(ay0, dA, 2 * lane + 1)
    DO_CH(ax1, dB, 64 + 2 * lane)
    DO_CH(ay1, dB, 65 + 2 * lane)
    if (lane < 16) {
        DO_CH(ax2, dC, 128 + 2 * lane)
        DO_CH(ay2, dC, 129 + 2 * lane)
    }
    #undef DO_CH
    #pragma unroll
    for (int h = 0; h < NH; h++)
        #pragma unroll
        for (int o = 16; o; o >>= 1) a2h[h] += __shfl_xor_sync(~0u, a2h[h], o);
    if (lane == 0) {
        float4 p0, p1, p2;
        p0.x = a2h[0]; p0.y = a2h[0] * __ldg(&as2w[0]);
        p0.z = a2h[1]; p0.w = a2h[1] * __ldg(&as2w[1]);
        p1.x = a2h[2]; p1.y = a2h[2] * __ldg(&as2w[2]);
        p1.z = a2h[3]; p1.w = a2h[3] * __ldg(&as2w[3]);
        p2.x = a2h[4]; p2.y = a2h[4] * __ldg(&as2w[4]);
        p2.z = 0.f; p2.w = 0.f;
        g_h2f4[n * 3 + 0] = p0;
        g_h2f4[n * 3 + 1] = p1;
        g_h2f4[n * 3 + 2] = p2;
        #pragma unroll
        for (int h = 0; h < NH; h++)
            g_ad2[n * NH + h] = a2h[h] * __ldg(&ad2w[h]);
    }
}

// ---- FUSED2: layer2 softmax+agg + head-mean + Wlin + sigmoid ----
__global__ void __launch_bounds__(256, 5)
k_fused2(const float* __restrict__ b2, const float* __restrict__ Wlin,
         float* __restrict__ out, int N) {
    int warp = (blockIdx.x * blockDim.x + threadIdx.x) >> 5;
    int lane = threadIdx.x & 31;
    if (warp >= N) return;
    int n = warp;
    int row = g_rowptr[n], end = g_rowptr[n + 1];

    float adh[NH], ceh[NH];
    #pragma unroll
    for (int h = 0; h < NH; h++) {
        adh[h] = __ldg(&g_ad2[n * NH + h]);
        ceh[h] = g_ce2[h];
    }
    float acch[NH] = {0.f, 0.f, 0.f, 0.f, 0.f};
    float denh[NH] = {0.f, 0.f, 0.f, 0.f, 0.f};

    for (int base = row; base < end; base += 32) {
        int e = base + lane;
        if (e < end) {
            int2 r = g_edge[e];
            int s = r.x;
            float av = __int_as_float(r.y);
            float4 p0 = __ldg(&g_h2f4[s * 3 + 0]);
            float4 p1 = __ldg(&g_h2f4[s * 3 + 1]);
            float4 p2 = __ldg(&g_h2f4[s * 3 + 2]);
            float h2v[NH]  = {p0.x, p0.z, p1.x, p1.z, p2.x};
            float as2v[NH] = {p0.y, p0.w, p1.y, p1.w, p2.y};
            #pragma unroll
            for (int h = 0; h < NH; h++) {
                float l = as2v[h] + adh[h] + av * ceh[h];
                l = l > 0.f ? l : 0.2f * l;
                float ex = __expf(l);
                denh[h] += ex;
                acch[h] = fmaf(ex, h2v[h], acch[h]);
            }
        }
    }
    #pragma unroll
    for (int h = 0; h < NH; h++)
        #pragma unroll
        for (int o = 16; o; o >>= 1) {
            acch[h] += __shfl_xor_sync(~0u, acch[h], o);
            denh[h] += __shfl_xor_sync(~0u, denh[h], o);
        }
    if (lane == 0) {
        float ssum = 0.f;
        #pragma unroll
        for (int h = 0; h < NH; h++) ssum += acch[h] / (denh[h] + 1e-16f);
        float y = (ssum * (1.0f / NH) + __ldg(&b2[0])) * __ldg(&Wlin[0]);
        out[n] = 1.0f / (1.0f + expf(-y));
    }
}

extern "C" void kernel_launch(void* const* d_in, const int* in_sizes, int n_in,
                              void* d_out, int out_size) {
    const float* x      = (const float*)d_in[0];
    const float* ea     = (const float*)d_in[1];
    const int*   src    = (const int*)d_in[2];
    const int*   dst    = (const int*)d_in[3];
    const float* W1     = (const float*)d_in[4];
    const float* a_src1 = (const float*)d_in[5];
    const float* a_dst1 = (const float*)d_in[6];
    const float* We1    = (const float*)d_in[7];
    const float* ae1    = (const float*)d_in[8];
    const float* b1     = (const float*)d_in[9];
    const float* W2     = (const float*)d_in[10];
    const float* a_src2 = (const float*)d_in[11];
    const float* a_dst2 = (const float*)d_in[12];
    const float* We2    = (const float*)d_in[13];
    const float* ae2    = (const float*)d_in[14];
    const float* b2     = (const float*)d_in[15];
    const float* Wlin   = (const float*)d_in[16];

    int N  = in_sizes[0] / 5;
    int E  = in_sizes[2];
    int E2 = E + N;
    float invE = 1.0f / (float)E;

    void* cntp = nullptr; void* easp = nullptr;
    cudaGetSymbolAddress(&cntp, g_cnt);
    cudaGetSymbolAddress(&easp, g_easum);
    cudaMemsetAsync(cntp, 0, N * sizeof(int));
    cudaMemsetAsync(easp, 0, sizeof(float));

    int countBlocks = (E2 + 255) / 256;
    int nodeBlocks  = (N * 32 + 255) / 256;
    k_combo<<<countBlocks + nodeBlocks, 256>>>(dst, ea, x, W1, a_src1, a_dst1, E, N, countBlocks);
    k_scan<<<1, 1024>>>(We1, ae1, We2, ae2, N, E2);
    k_scatter<<<(E2 + 255) / 256, 256>>>(src, dst, ea, E, N, invE);
    k_fused1<<<(N * 32 + 255) / 256, 256>>>(b1, W2, a_src2, a_dst2, N);
    k_fused2<<<(N * 32 + 255) / 256, 256>>>(b2, Wlin, (float*)d_out, N);
}

// round 9
// speedup vs baseline: 1.1517x; 1.0193x over previous
#include <cuda_runtime.h>
#include <cuda_fp16.h>

#define NMAX 50000
#define EMAX 800000
#define E2MAX (EMAX + NMAX)
#define HC 160
#define HCP 192   // padded h1 row: 384 B, 128B-aligned
#define NH 5
#define NC 32
#define WPB 8

// ---- scratch (static device globals) ----
__device__ __align__(128) __half g_h1h[(size_t)NMAX * HCP];
__device__ __align__(16) __half g_as1h[NMAX * 8];   // as1 (fp16), 16B/node
__device__ float g_ad1[NMAX * NH];
__device__ __align__(16) __half g_h2h[NMAX * 8];    // h2 (fp16), 16B/node
__device__ float g_ad2[NMAX * NH];
__device__ float g_ce1[NH], g_ce2[NH];
__device__ float g_easum;
__device__ int   g_cnt[NMAX];
__device__ int   g_rowptr[NMAX + 1];
__device__ int   g_pos[E2MAX];
__device__ __align__(8) int2 g_edge[E2MAX];         // {src, ea-bits}

// ---- combo: [count in-degree (save pos) + easum] || [node1 transform] ----
__global__ void k_combo(const int* __restrict__ dst, const float* __restrict__ ea,
                        const float* __restrict__ x, const float* __restrict__ W1,
                        const float* __restrict__ asrc, const float* __restrict__ adst,
                        int E, int N, int countBlocks) {
    if ((int)blockIdx.x < countBlocks) {
        int e = blockIdx.x * blockDim.x + threadIdx.x;
        int E2 = E + N;
        float s = 0.f;
        if (e < E2) {
            int d = (e < E) ? __ldg(&dst[e]) : (e - E);
            g_pos[e] = atomicAdd(&g_cnt[d], 1);
            if (e < E) s = __ldg(&ea[e]);
        }
        #pragma unroll
        for (int o = 16; o; o >>= 1) s += __shfl_xor_sync(~0u, s, o);
        if ((threadIdx.x & 31) == 0 && s != 0.f) atomicAdd(&g_easum, s);
    } else {
        int warp = (((int)blockIdx.x - countBlocks) * blockDim.x + threadIdx.x) >> 5;
        int lane = threadIdx.x & 31;
        if (warp >= N) return;
        int n = warp;
        float xf[5];
        #pragma unroll
        for (int f = 0; f < 5; f++) xf[f] = __ldg(&x[n * 5 + f]);
        #pragma unroll
        for (int h = 0; h < NH; h++) {
            int col = h * NC + lane;
            float acc = 0.f;
            #pragma unroll
            for (int f = 0; f < 5; f++) acc = fmaf(xf[f], __ldg(&W1[f * HC + col]), acc);
            g_h1h[(size_t)n * HCP + col] = __float2half(acc);
            float ps = acc * __ldg(&asrc[col]);
            float pd = acc * __ldg(&adst[col]);
            #pragma unroll
            for (int o = 16; o; o >>= 1) {
                ps += __shfl_xor_sync(~0u, ps, o);
                pd += __shfl_xor_sync(~0u, pd, o);
            }
            if (lane == 0) {
                g_as1h[n * 8 + h] = __float2half(ps);
                g_ad1[n * NH + h] = pd;
            }
        }
        if (lane == 0) {
            g_as1h[n * 8 + 5] = __float2half(0.f);
            g_as1h[n * 8 + 6] = __float2half(0.f);
            g_as1h[n * 8 + 7] = __float2half(0.f);
        }
    }
}

// ---- single-block exclusive scan + attn constants ----
__global__ void k_scan(const float* __restrict__ We1, const float* __restrict__ ae1,
                       const float* __restrict__ We2, const float* __restrict__ ae2,
                       int N, int E2) {
    __shared__ int wsum[32];
    int t = threadIdx.x;
    int lane = t & 31, w = t >> 5;
    if (t < NH) {
        float s = 0.f;
        for (int c = 0; c < NC; c++) s += We1[t * NC + c] * ae1[t * NC + c];
        g_ce1[t] = s;
        g_ce2[t] = We2[t] * ae2[t];
    }
    int chunk = (N + 1023) / 1024;
    int b = t * chunk, e = min(b + chunk, N);
    int s = 0;
    for (int i = b; i < e; i++) s += g_cnt[i];
    int inc = s;
    #pragma unroll
    for (int o = 1; o < 32; o <<= 1) {
        int v = __shfl_up_sync(~0u, inc, o);
        if (lane >= o) inc += v;
    }
    if (lane == 31) wsum[w] = inc;
    __syncthreads();
    if (w == 0) {
        int v = wsum[lane];
        int iv = v;
        #pragma unroll
        for (int o = 1; o < 32; o <<= 1) {
            int u = __shfl_up_sync(~0u, iv, o);
            if (lane >= o) iv += u;
        }
        wsum[lane] = iv - v;
    }
    __syncthreads();
    int run = wsum[w] + inc - s;
    for (int i = b; i < e; i++) {
        g_rowptr[i] = run;
        run += g_cnt[i];
    }
    if (t == 0) g_rowptr[N] = E2;
}

// ---- scatter edges into CSR: atomic-free ----
__global__ void k_scatter(const int* __restrict__ src, const int* __restrict__ dst,
                          const float* __restrict__ ea, int E, int N, float invE) {
    int e = blockIdx.x * blockDim.x + threadIdx.x;
    int E2 = E + N;
    if (e >= E2) return;
    int s, d; float av;
    if (e < E) { s = __ldg(&src[e]); d = __ldg(&dst[e]); av = __ldg(&ea[e]); }
    else       { s = d = e - E; av = g_easum * invE; }
    int2 rec; rec.x = s; rec.y = __float_as_int(av);
    g_edge[__ldg(&g_rowptr[d]) + g_pos[e]] = rec;
}

// ---- FUSED1: layer1 softmax+agg + relu + layer2 transform ----
__global__ void __launch_bounds__(256, 5)
k_fused1(const float* __restrict__ b1, const float* __restrict__ W2,
         const float* __restrict__ as2w, const float* __restrict__ ad2w,
         int N) {
    __shared__ __align__(16) float s_rec[WPB][32][8];
    int warp = (blockIdx.x * blockDim.x + threadIdx.x) >> 5;
    int lane = threadIdx.x & 31;
    int w = (threadIdx.x >> 5);
    if (warp >= N) return;
    int n = warp;
    int row = g_rowptr[n], end = g_rowptr[n + 1];

    float adh[NH], ceh[NH];
    #pragma unroll
    for (int h = 0; h < NH; h++) {
        adh[h] = __ldg(&g_ad1[n * NH + h]);
        ceh[h] = g_ce1[h];
    }
    int hA = lane >> 4;

    float ax0 = 0.f, ay0 = 0.f, ax1 = 0.f, ay1 = 0.f, ax2 = 0.f, ay2 = 0.f;
    float denh[NH] = {0.f, 0.f, 0.f, 0.f, 0.f};

    for (int base = row; base < end; base += 32) {
        int cnt = min(32, end - base);
        if (lane < cnt) {
            int2 r = g_edge[base + lane];
            int sA = r.x;
            float av = __int_as_float(r.y);
            int4 va = __ldg((const int4*)(g_as1h + sA * 8));
            float2 f01 = __half22float2(*(__half2*)&va.x);
            float2 f23 = __half22float2(*(__half2*)&va.y);
            float2 f45 = __half22float2(*(__half2*)&va.z);
            float lv[NH] = {f01.x, f01.y, f23.x, f23.y, f45.x};
            float ex[NH];
            #pragma unroll
            for (int h = 0; h < NH; h++) {
                float l = lv[h] + adh[h] + av * ceh[h];
                l = l > 0.f ? l : 0.2f * l;
                ex[h] = __expf(l);
                denh[h] += ex[h];
            }
            float2* rec = (float2*)s_rec[w][lane];
            float2 p0; p0.x = ex[0]; p0.y = ex[2];
            float2 p1; p1.x = ex[1]; p1.y = ex[3];
            float2 p2; p2.x = ex[4]; p2.y = __int_as_float(sA);
            rec[0] = p0; rec[1] = p1; rec[2] = p2;
        }
        __syncwarp();
        #pragma unroll 2
        for (int j = 0; j < cnt; j++) {
            float2 pab = *(const float2*)&s_rec[w][j][2 * hA];
            float2 p4s = *(const float2*)&s_rec[w][j][4];
            int s = __float_as_int(p4s.y);
            float a0 = pab.x, a1 = pab.y, a2 = p4s.x;
            const __half2* hb = (const __half2*)(g_h1h + (size_t)s * HCP);
            __half2 v0 = __ldg(&hb[lane]);
            __half2 v1 = __ldg(&hb[32 + lane]);
            float2 f0 = __half22float2(v0), f1 = __half22float2(v1);
            ax0 = fmaf(a0, f0.x, ax0); ay0 = fmaf(a0, f0.y, ay0);
            ax1 = fmaf(a1, f1.x, ax1); ay1 = fmaf(a1, f1.y, ay1);
            if (lane < 16) {
                __half2 v2 = __ldg(&hb[64 + lane]);
                float2 f2 = __half22float2(v2);
                ax2 = fmaf(a2, f2.x, ax2); ay2 = fmaf(a2, f2.y, ay2);
            }
        }
        __syncwarp();
    }

    #pragma unroll
    for (int h = 0; h < NH; h++) {
        #pragma unroll
        for (int o = 16; o; o >>= 1) denh[h] += __shfl_xor_sync(~0u, denh[h], o);
        denh[h] += 1e-16f;
    }
    float dA = denh[hA], dB = denh[2 + hA], dC = denh[4];

    float a2h[NH] = {0.f, 0.f, 0.f, 0.f, 0.f};
    int k; float v;
    #define DO_CH(val, dd, kk) \
        k = (kk); v = (val) / (dd) + __ldg(&b1[k]); v = fmaxf(v, 0.f); \
        _Pragma("unroll") \
        for (int h = 0; h < NH; h++) a2h[h] = fmaf(v, __ldg(&W2[k * NH + h]), a2h[h]);
    DO_CH(ax0, dA, 2 * lane)
    DO_CH(ay0, dA, 2 * lane + 1)
    DO_CH(ax1, dB, 64 + 2 * lane)
    DO_CH(ay1, dB, 65 + 2 * lane)
    if (lane < 16) {
        DO_CH(ax2, dC, 128 + 2 * lane)
        DO_CH(ay2, dC, 129 + 2 * lane)
    }
    #undef DO_CH
    #pragma unroll
    for (int h = 0; h < NH; h++)
        #pragma unroll
        for (int o = 16; o; o >>= 1) a2h[h] += __shfl_xor_sync(~0u, a2h[h], o);
    if (lane == 0) {
        // h2 packed as 8 halves (one 16B record)
        __half2 q0 = __floats2half2_rn(a2h[0], a2h[1]);
        __half2 q1 = __floats2half2_rn(a2h[2], a2h[3]);
        __half2 q2 = __floats2half2_rn(a2h[4], 0.f);
        __half2 q3 = __floats2half2_rn(0.f, 0.f);
        int4 pk;
        pk.x = *(int*)&q0; pk.y = *(int*)&q1; pk.z = *(int*)&q2; pk.w = *(int*)&q3;
        *(int4*)(g_h2h + n * 8) = pk;
        #pragma unroll
        for (int h = 0; h < NH; h++)
            g_ad2[n * NH + h] = a2h[h] * __ldg(&ad2w[h]);
    }
}

// ---- FUSED2: layer2 softmax+agg + head-mean + Wlin + sigmoid ----
// per-edge scattered traffic: ONE 16B load (h2 fp16); as2 derived in-flight.
__global__ void k_fused2(const float* __restrict__ as2w,
                         const float* __restrict__ b2, const float* __restrict__ Wlin,
                         float* __restrict__ out, int N) {
    int warp = (blockIdx.x * blockDim.x + threadIdx.x) >> 5;
    int lane = threadIdx.x & 31;
    if (warp >= N) return;
    int n = warp;
    int row = g_rowptr[n], end = g_rowptr[n + 1];

    float adh[NH], ceh[NH], aw[NH];
    #pragma unroll
    for (int h = 0; h < NH; h++) {
        adh[h] = __ldg(&g_ad2[n * NH + h]);
        ceh[h] = g_ce2[h];
        aw[h]  = __ldg(&as2w[h]);
    }
    float acch[NH] = {0.f, 0.f, 0.f, 0.f, 0.f};
    float denh[NH] = {0.f, 0.f, 0.f, 0.f, 0.f};

    for (int base = row; base < end; base += 32) {
        int e = base + lane;
        if (e < end) {
            int2 r = g_edge[e];
            int s = r.x;
            float av = __int_as_float(r.y);
            int4 vp = __ldg((const int4*)(g_h2h + s * 8));
            float2 f01 = __half22float2(*(__half2*)&vp.x);
            float2 f23 = __half22float2(*(__half2*)&vp.y);
            float2 f45 = __half22float2(*(__half2*)&vp.z);
            float h2v[NH] = {f01.x, f01.y, f23.x, f23.y, f45.x};
            #pragma unroll
            for (int h = 0; h < NH; h++) {
                float l = fmaf(h2v[h], aw[h], adh[h] + av * ceh[h]);
                l = l > 0.f ? l : 0.2f * l;
                float ex = __expf(l);
                denh[h] += ex;
                acch[h] = fmaf(ex, h2v[h], acch[h]);
            }
        }
    }
    #pragma unroll
    for (int h = 0; h < NH; h++)
        #pragma unroll
        for (int o = 16; o; o >>= 1) {
            acch[h] += __shfl_xor_sync(~0u, acch[h], o);
            denh[h] += __shfl_xor_sync(~0u, denh[h], o);
        }
    if (lane == 0) {
        float ssum = 0.f;
        #pragma unroll
        for (int h = 0; h < NH; h++) ssum += acch[h] / (denh[h] + 1e-16f);
        float y = (ssum * (1.0f / NH) + __ldg(&b2[0])) * __ldg(&Wlin[0]);
        out[n] = 1.0f / (1.0f + expf(-y));
    }
}

extern "C" void kernel_launch(void* const* d_in, const int* in_sizes, int n_in,
                              void* d_out, int out_size) {
    const float* x      = (const float*)d_in[0];
    const float* ea     = (const float*)d_in[1];
    const int*   src    = (const int*)d_in[2];
    const int*   dst    = (const int*)d_in[3];
    const float* W1     = (const float*)d_in[4];
    const float* a_src1 = (const float*)d_in[5];
    const float* a_dst1 = (const float*)d_in[6];
    const float* We1    = (const float*)d_in[7];
    const float* ae1    = (const float*)d_in[8];
    const float* b1     = (const float*)d_in[9];
    const float* W2     = (const float*)d_in[10];
    const float* a_src2 = (const float*)d_in[11];
    const float* a_dst2 = (const float*)d_in[12];
    const float* We2    = (const float*)d_in[13];
    const float* ae2    = (const float*)d_in[14];
    const float* b2     = (const float*)d_in[15];
    const float* Wlin   = (const float*)d_in[16];

    int N  = in_sizes[0] / 5;
    int E  = in_sizes[2];
    int E2 = E + N;
    float invE = 1.0f / (float)E;

    void* cntp = nullptr; void* easp = nullptr;
    cudaGetSymbolAddress(&cntp, g_cnt);
    cudaGetSymbolAddress(&easp, g_easum);
    cudaMemsetAsync(cntp, 0, N * sizeof(int));
    cudaMemsetAsync(easp, 0, sizeof(float));

    int countBlocks = (E2 + 255) / 256;
    int nodeBlocks  = (N * 32 + 255) / 256;
    k_combo<<<countBlocks + nodeBlocks, 256>>>(dst, ea, x, W1, a_src1, a_dst1, E, N, countBlocks);
    k_scan<<<1, 1024>>>(We1, ae1, We2, ae2, N, E2);
    k_scatter<<<(E2 + 255) / 256, 256>>>(src, dst, ea, E, N, invE);
    k_fused1<<<(N * 32 + 255) / 256, 256>>>(b1, W2, a_src2, a_dst2, N);
    k_fused2<<<(N * 32 + 255) / 256, 256>>>(a_src2, b2, Wlin, (float*)d_out, N);
}